// round 17
// baseline (speedup 1.0000x reference)
#include <cuda_runtime.h>
#include <cuda.h>
#include <cuda_bf16.h>
#include <cstdint>

// PrRoIPool2D(7,7, spatial_scale=0.5)
// features: (8, 256, 56, 56) f32 ; rois: (256,5) ; out: (256,256,7,7) f32

#define POOLED 7
#define SCALE 0.5f
#define CC 256
#define HH 56
#define WW 56
#define NTHR 128        // 32 channels x 4 pw-pair groups

__device__ __forceinline__ float tentG(float t) {
    float u;
    if (t <= 0.0f) { u = t + 1.0f; return 0.5f * u * u; }
    u = 1.0f - t;
    return 1.0f - 0.5f * u * u;
}
__device__ __forceinline__ float tent_int(float s, float e, float i) {
    float a = fminf(fmaxf(s - i, -1.0f), 1.0f);
    float b = fminf(fmaxf(e - i, -1.0f), 1.0f);
    return tentG(b) - tentG(a);
}

// ---------------- mbarrier / TMA helpers ----------------
__device__ __forceinline__ void mbar_init(uint32_t a, uint32_t cnt) {
    asm volatile("mbarrier.init.shared.b64 [%0], %1;" :: "r"(a), "r"(cnt) : "memory");
}
__device__ __forceinline__ void mbar_expect(uint32_t a, uint32_t bytes) {
    asm volatile("mbarrier.arrive.expect_tx.shared.b64 _, [%0], %1;"
                 :: "r"(a), "r"(bytes) : "memory");
}
__device__ __forceinline__ void mbar_wait(uint32_t a, uint32_t parity) {
    asm volatile(
        "{\n\t.reg .pred P;\n\t"
        "MBWAIT_%=:\n\t"
        "mbarrier.try_wait.parity.acquire.cta.shared::cta.b64 P, [%0], %1, 0x989680;\n\t"
        "@!P bra MBWAIT_%=;\n\t}"
        :: "r"(a), "r"(parity) : "memory");
}
__device__ __forceinline__ void tma3d(uint32_t dst, const void* tmap,
                                      int x, int y, int z, uint32_t mbar) {
    asm volatile(
        "cp.async.bulk.tensor.3d.shared::cta.global.tile.mbarrier::complete_tx::bytes "
        "[%0], [%1, {%2, %3, %4}], [%5];"
        :: "r"(dst), "l"(tmap), "r"(x), "r"(y), "r"(z), "r"(mbar) : "memory");
}
__device__ __forceinline__ void fence_proxy() {
    asm volatile("fence.proxy.async.shared::cta;" ::: "memory");
}

// 4 ring buffers x 2 rows x 4KB (32 channels, SW128-swizzled by TMA), depth-3 pipeline.
struct alignas(1024) SmemT {
    char  sbuf[4 * 2 * 4096];         // 32 KB
    float iy[28][8];                  // per-ROI y weights (1/area folded), zero-padded
    float ixw[4][2][12];              // pair g, bin{2g,2g+1}, 12 taps
    unsigned long long mbar[4];
};

// ---- templated unit: mbar init, table fill, deep TMA pipeline, main loop ----
template<int NJ>
__device__ __forceinline__ void run_unit(
    SmemT& sm, const void* tmapp,
    int x0, int zb, int hlo, int hhi, int cl, int g, int prel, int tid,
    int base4, int p0, int p1, int p2, int p3,
    float rx1, float bw, float ry1, float bh, float sc,
    float (&acc0)[POOLED], float (&acc1)[POOLED])
{
    const uint32_t mbb = (uint32_t)__cvta_generic_to_shared(&sm.mbar[0]);
    const uint32_t sb  = (uint32_t)__cvta_generic_to_shared(sm.sbuf);

    if (tid == 0) {
        mbar_init(mbb,      1);
        mbar_init(mbb + 8,  1);
        mbar_init(mbb + 16, 1);
        mbar_init(mbb + 24, 1);
        fence_proxy();
    }

    // ---- fill weight tables in smem ----
    if (tid < 96) {
        const int g4 = tid / 24, rem = tid - g4 * 24, bin = rem / 12, k = rem - bin * 12;
        const int pr = (g4 == 0) ? p0 : (g4 == 1) ? p1 : (g4 == 2) ? p2 : p3;
        const int q = 2 * g4 + bin;
        float v = 0.0f;
        if (q < POOLED) {
            const int w = (base4 + pr) * 4 + k;
            if (w < WW) {
                const float xs = rx1 + q * bw;
                v = tent_int(xs, xs + bw, (float)w);
            }
        }
        sm.ixw[g4][bin][k] = v;
    }
    for (int e = tid; e < 28 * 8; e += NTHR) {
        const int hr = e >> 3, j = e & 7;
        const int h = hlo + hr;
        float v = 0.0f;
        if (j < POOLED && h <= hhi) {
            const float ys = ry1 + j * bh;
            v = sc * tent_int(ys, ys + bh, (float)h);
        }
        sm.iy[hr][j] = v;
    }
    __syncthreads();   // tables + mbar init visible

    // prologue: issue groups 0..2 (2 rows each), only if that iteration exists.
    // Rows beyond hhi (or >= HH): TMA OOB zero-fill + iy==0 -> zero contribution.
    if (tid == 0) {
        mbar_expect(mbb, 8192);
        tma3d(sb,         tmapp, x0, hlo,     zb, mbb);
        tma3d(sb + 4096,  tmapp, x0, hlo + 1, zb, mbb);
        if (hlo + 2 <= hhi) {
            mbar_expect(mbb + 8, 8192);
            tma3d(sb + 8192,  tmapp, x0, hlo + 2, zb, mbb + 8);
            tma3d(sb + 12288, tmapp, x0, hlo + 3, zb, mbb + 8);
        }
        if (hlo + 4 <= hhi) {
            mbar_expect(mbb + 16, 8192);
            tma3d(sb + 16384, tmapp, x0, hlo + 4, zb, mbb + 16);
            tma3d(sb + 20480, tmapp, x0, hlo + 5, zb, mbb + 16);
        }
    }

    // pair weights into registers (broadcast LDS)
    float4 w0[NJ], w1[NJ];
    const float4* wp = (const float4*)&sm.ixw[g][0][0];
#pragma unroll
    for (int m = 0; m < NJ; ++m) { w0[m] = wp[m]; w1[m] = wp[3 + m]; }

    // SW128 reader offsets: smem row = channel cl; chunk q lands at q ^ (cl&7)
    uint32_t co[NJ];
#pragma unroll
    for (int j = 0; j < NJ; ++j)
        co[j] = (uint32_t)(((prel + j) ^ (cl & 7)) << 4);
    const char* cbase = sm.sbuf + cl * 128;

    int it = 0;
    for (int h = hlo; h <= hhi; h += 2, ++it) {
        const int p = it & 3;
        const uint32_t mb = mbb + (uint32_t)(p << 3);
        mbar_wait(mb, (uint32_t)((it >> 2) & 1));   // depth-3: usually fast path

        const int hr = h - hlo;
        const float4 ya0 = *(const float4*)&sm.iy[hr][0];
        const float4 yb0 = *(const float4*)&sm.iy[hr][4];
        const float4 ya1 = *(const float4*)&sm.iy[hr + 1][0];
        const float4 yb1 = *(const float4*)&sm.iy[hr + 1][4];

#pragma unroll
        for (int rr = 0; rr < 2; ++rr) {
            const char* rbase = cbase + (uint32_t)(p * 2 + rr) * 4096u;
            float s0 = 0.0f, s1 = 0.0f;
#pragma unroll
            for (int j = 0; j < NJ; ++j) {
                const float4 x = *(const float4*)(rbase + co[j]);
                s0 = fmaf(x.x, w0[j].x, s0); s0 = fmaf(x.y, w0[j].y, s0);
                s0 = fmaf(x.z, w0[j].z, s0); s0 = fmaf(x.w, w0[j].w, s0);
                s1 = fmaf(x.x, w1[j].x, s1); s1 = fmaf(x.y, w1[j].y, s1);
                s1 = fmaf(x.z, w1[j].z, s1); s1 = fmaf(x.w, w1[j].w, s1);
            }
            // guarded y accumulation (uniform predicates; iy zero-padded past hhi)
            const float4 ya = rr ? ya1 : ya0;
            const float4 yb = rr ? yb1 : yb0;
            if (ya.x != 0.0f) { acc0[0] = fmaf(ya.x, s0, acc0[0]); acc1[0] = fmaf(ya.x, s1, acc1[0]); }
            if (ya.y != 0.0f) { acc0[1] = fmaf(ya.y, s0, acc0[1]); acc1[1] = fmaf(ya.y, s1, acc1[1]); }
            if (ya.z != 0.0f) { acc0[2] = fmaf(ya.z, s0, acc0[2]); acc1[2] = fmaf(ya.z, s1, acc1[2]); }
            if (ya.w != 0.0f) { acc0[3] = fmaf(ya.w, s0, acc0[3]); acc1[3] = fmaf(ya.w, s1, acc1[3]); }
            if (yb.x != 0.0f) { acc0[4] = fmaf(yb.x, s0, acc0[4]); acc1[4] = fmaf(yb.x, s1, acc1[4]); }
            if (yb.y != 0.0f) { acc0[5] = fmaf(yb.y, s0, acc0[5]); acc1[5] = fmaf(yb.y, s1, acc1[5]); }
            if (yb.z != 0.0f) { acc0[6] = fmaf(yb.z, s0, acc0[6]); acc1[6] = fmaf(yb.z, s1, acc1[6]); }
        }

        __syncthreads();   // all reads through iter `it` done -> safe to refill (p+3)&3
        if (tid == 0 && h + 6 <= hhi) {
            const int np = (p + 3) & 3;                      // buffer of group it+3
            const uint32_t nmb = mbb + (uint32_t)(np << 3);
            const uint32_t dA = sb + (uint32_t)(np * 2) * 4096u;
            mbar_expect(nmb, 8192);
            tma3d(dA,        tmapp, x0, h + 6, zb, nmb);
            tma3d(dA + 4096, tmapp, x0, h + 7, zb, nmb);
        }
    }
}

// ---------------- fused kernel: 128 thr = 32 ch x 4 pw-pairs; grid = R*8 ----------------
__global__ __launch_bounds__(NTHR, 6)
void prroi_main(const __grid_constant__ CUtensorMap tmap,
                const float* __restrict__ rois, float* __restrict__ out)
{
    const int bid = blockIdx.x;
    const int r    = bid >> 3;
    const int c0   = (bid & 7) << 5;          // 32-channel slab
    const int tid  = threadIdx.x;
    const int cl   = tid & 31;                // channel lane
    const int g    = tid >> 5;                // pw-pair group == warp id

    __shared__ SmemT sm;

    // ---- per-ROI meta (uniform; broadcast loads) ----
    const float rb  = __ldg(&rois[r * 5 + 0]);
    const float rx1 = __ldg(&rois[r * 5 + 1]) * SCALE;
    const float ry1 = __ldg(&rois[r * 5 + 2]) * SCALE;
    const float rx2 = __ldg(&rois[r * 5 + 3]) * SCALE;
    const float ry2 = __ldg(&rois[r * 5 + 4]) * SCALE;
    const int   b   = (int)rb;
    const float bw = (rx2 - rx1) * (1.0f / POOLED);
    const float bh = (ry2 - ry1) * (1.0f / POOLED);
    const float area = bw * bh;
    const float sc = (area > 0.0f) ? (1.0f / fmaxf(area, 1e-12f)) : 0.0f;

    int wlo = (int)ceilf(rx1 - 1.0f); if (wlo < 0) wlo = 0;
    const int base4 = (wlo & ~3) >> 2;                    // <= 13
    int hlo = (int)ceilf(ry1 - 1.0f);  if (hlo < 0) hlo = 0;
    int hhi = (int)floorf(ry2 + 1.0f); if (hhi > HH - 1) hhi = HH - 1;
    if (hhi < hlo) hhi = hlo;

    // per-pair relative chunk base within the 8-chunk window + 8-tap qualification
    int pr[4]; int ok8 = 1;
#pragma unroll
    for (int gg = 0; gg < 4; ++gg) {
        const float xs = rx1 + (2 * gg) * bw;
        int pb = (int)ceilf(xs - 1.0f); if (pb < 0) pb = 0;
        int pb4 = (pb & ~3) >> 2; if (pb4 > 13) pb4 = 13;
        int rel = pb4 - base4;
        if (rel < 0) rel = 0;
        if (rel > 5) rel = 5;      // window rel..rel+2 stays within 8 chunks
        pr[gg] = rel;
        const float e = xs + ((gg < 3) ? 2.0f * bw : bw);
        int whi = (int)floorf(e + 1.0f); if (whi > WW - 1) whi = WW - 1;
        if (whi - (base4 + rel) * 4 > 7) ok8 = 0;
    }
    const int p0 = pr[0], p1 = pr[1], p2 = pr[2], p3 = pr[3];
    const int prel = (g == 0) ? p0 : (g == 1) ? p1 : (g == 2) ? p2 : p3;

    const int x0 = base4 * 4;                 // element x of TMA box (OOB -> zeros)
    const int zb = b * CC + c0;               // channel-plane coordinate

    float acc0[POOLED], acc1[POOLED];
#pragma unroll
    for (int k = 0; k < POOLED; ++k) { acc0[k] = 0.0f; acc1[k] = 0.0f; }

    const void* tp = (const void*)&tmap;
    if (ok8) run_unit<2>(sm, tp, x0, zb, hlo, hhi, cl, g, prel, tid,
                         base4, p0, p1, p2, p3, rx1, bw, ry1, bh, sc, acc0, acc1);
    else     run_unit<3>(sm, tp, x0, zb, hlo, hhi, cl, g, prel, tid,
                         base4, p0, p1, p2, p3, rx1, bw, ry1, bh, sc, acc0, acc1);

    __syncthreads();   // all reads done before reusing smem for output gather

    // ---- gather to smem, write coalesced ----
    float* sout = (float*)&sm;                // >= 1568 floats available
    const int pw0 = 2 * g;
#pragma unroll
    for (int ph = 0; ph < POOLED; ++ph) {
        sout[cl * 49 + ph * 7 + pw0] = acc0[ph];
        if (pw0 + 1 < POOLED) sout[cl * 49 + ph * 7 + pw0 + 1] = acc1[ph];
    }
    __syncthreads();

    float4* o4 = (float4*)(out + ((size_t)r * CC + c0) * 49);
    const float4* s4 = (const float4*)sout;
#pragma unroll
    for (int k = 0; k < 3; ++k)
        o4[tid + NTHR * k] = s4[tid + NTHR * k];       // 384 float4
    if (tid < 8) o4[384 + tid] = s4[384 + tid];        // -> 392 = 1568 floats
}

extern "C" void kernel_launch(void* const* d_in, const int* in_sizes, int n_in,
                              void* d_out, int out_size) {
    const float* feat = (const float*)d_in[0];
    const float* rois = (const float*)d_in[1];
    float* out = (float*)d_out;
    const int R = in_sizes[1] / 5;
    const cuuint64_t nc = (cuuint64_t)in_sizes[0] / (HH * WW);   // N*C planes

    // Build the tensor map host-side each call (deterministic; no allocation).
    typedef CUresult (*PFN_encode)(CUtensorMap*, CUtensorMapDataType, cuuint32_t, void*,
        const cuuint64_t*, const cuuint64_t*, const cuuint32_t*, const cuuint32_t*,
        CUtensorMapInterleave, CUtensorMapSwizzle, CUtensorMapL2promotion,
        CUtensorMapFloatOOBfill);
    void* fp = nullptr;
#if CUDART_VERSION >= 12050
    cudaDriverEntryPointQueryResult qres;
    cudaGetDriverEntryPointByVersion("cuTensorMapEncodeTiled", &fp, 12000,
                                     cudaEnableDefault, &qres);
#else
    cudaDriverEntryPointQueryResult qres;
    cudaGetDriverEntryPoint("cuTensorMapEncodeTiled", &fp, cudaEnableDefault, &qres);
#endif
    CUtensorMap tmap;
    cuuint64_t dims[3]    = { WW, HH, nc };
    cuuint64_t strides[2] = { WW * 4ull, (cuuint64_t)HH * WW * 4ull };
    cuuint32_t box[3]     = { 32, 1, 32 };     // 128B x-window, 1 row, 32 channels
    cuuint32_t estr[3]    = { 1, 1, 1 };
    ((PFN_encode)fp)(&tmap, CU_TENSOR_MAP_DATA_TYPE_FLOAT32, 3, (void*)feat,
                     dims, strides, box, estr,
                     CU_TENSOR_MAP_INTERLEAVE_NONE, CU_TENSOR_MAP_SWIZZLE_128B,
                     CU_TENSOR_MAP_L2_PROMOTION_L2_128B,
                     CU_TENSOR_MAP_FLOAT_OOB_FILL_NONE);

    prroi_main<<<R * 8, NTHR>>>(tmap, rois, out);
}